// round 3
// baseline (speedup 1.0000x reference)
#include <cuda_runtime.h>

// ---------------------------------------------------------------------------
//   x:     (16, 32, 32, 32, 32) fp32
//   w:     (32, 16, 3, 3, 3)    fp32   (Cin, Cout, kd, kh, kw)
//   b, gamma, beta: (16,) fp32
//   ConvTranspose3d stride=2 pad=1 -> y (16,16,63,63,63)
//   BN over (N,D,H,W) per channel, AvgPool 4 (floor) -> (16,16,15,15,15)
//
// Parity decomposition (per axis): output o = 2*o2 + p.
//   p=0: 1 tap  (k=1, i=o2)        p=1: 2 taps (k=2,i=o2 ; k=0,i=o2+1)
// No boundary masking needed except the o=63 edge (masked per axis).
// Pool index: o/4 == a for o in [4a, 4a+3], i.e. od2 in {2a, 2a+1}, both
// parities -> a block owning od2 {2a,2a+1} across all 8 classes owns pool
// slice a exclusively. Pool sums accumulate in registers; raw sums are
// written once to d_out and the BN affine (which commutes with mean-pool)
// is applied in place by a tiny final kernel.
// ---------------------------------------------------------------------------

static __device__ float g_sum[16];
static __device__ float g_sumsq[16];
static __device__ float g_scale[16];
static __device__ float g_shift[16];

__global__ void zero_stats_kernel() {
    int t = threadIdx.x;
    if (t < 16) { g_sum[t] = 0.f; g_sumsq[t] = 0.f; }
}

// Grid: x = half4 (4: oh2 octet), y = a (16: od2 pair / pool-d), z = n (16).
// Block (32, 4). Thread: lane = ow2, warp ty -> oh2 rows {base, base+1},
// 16 cout scalar accumulators per row, looped over 8 classes x 2 od2.
__global__ __launch_bounds__(128, 2)
void conv_kernel(const float* __restrict__ x,
                 const float* __restrict__ w,
                 const float* __restrict__ bias,
                 float* __restrict__ out)
{
    const int half4 = blockIdx.x;
    const int a     = blockIdx.y;
    const int n     = blockIdx.z;
    const int tx = threadIdx.x, ty = threadIdx.y;
    const int tid = ty * 32 + tx;
    const int ow2 = tx;
    const int oh2b = half4 * 8 + 2 * ty;      // even, 0..30

    __shared__ __align__(16) float ws[8 * 512];
    __shared__ float sred[32];
    __shared__ float bsh[16];

    if (tid < 32) sred[tid] = 0.f;
    if (tid < 16) bsh[tid] = bias[tid];

    float ssum[16], ssq[16], pacc[16];
#pragma unroll
    for (int c = 0; c < 16; c++) { ssum[c] = 0.f; ssq[c] = 0.f; pacc[c] = 0.f; }

    const bool poolok = (a < 15) && (oh2b < 30) && (ow2 < 30);

    for (int cls = 0; cls < 8; cls++) {
        const int pd = (cls >> 2) & 1, ph = (cls >> 1) & 1, pw = cls & 1;
        const int ntd = 1 + pd, nth = 1 + ph, ntw = 1 + pw;
        const int ntap = ntd * nth * ntw;

        __syncthreads();
        for (int i = tid; i < ntap * 512; i += 128) {
            int t = i >> 9, e = i & 511;
            int tw = t % ntw, th = (t / ntw) % nth, td = t / (ntw * nth);
            int kd = pd ? 2 - 2 * td : 1;
            int kh = ph ? 2 - 2 * th : 1;
            int kw = pw ? 2 - 2 * tw : 1;
            int ci = e >> 4, co = e & 15;
            ws[i] = w[(ci * 16 + co) * 27 + kd * 9 + kh * 3 + kw];
        }
        __syncthreads();

        const bool vlane = (!pw) || (ow2 < 31);       // ow = 2*ow2+pw <= 62
        const bool v1row = (!ph) || (oh2b + 1 < 31);  // row-1 oh <= 62
        const int  owS   = vlane ? ow2 : 0;           // clamp loads in-bounds
        const int  r1off = v1row ? 32 : 0;

        for (int dd = 0; dd < 2; dd++) {
            const int od2 = 2 * a + dd;
            if (pd && od2 == 31) continue;            // od = 63 (uniform skip)

            float acc0[16], acc1[16];
#pragma unroll
            for (int c = 0; c < 16; c++) { acc0[c] = bsh[c]; acc1[c] = bsh[c]; }

            for (int td = 0; td < ntd; td++) {
                const int id = od2 + (pd ? td : 0);
                for (int th = 0; th < nth; th++) {
                    const int ih0 = oh2b + (ph ? th : 0);
                    for (int tw = 0; tw < ntw; tw++) {
                        const int iw = owS + (pw ? tw : 0);
                        const int tap = (td * nth + th) * ntw + tw;
                        const float* wp = ws + tap * 512;
                        const float* xp = x + (size_t)n * 1048576
                                            + (size_t)id * 1024 + ih0 * 32 + iw;
#pragma unroll 4
                        for (int ci = 0; ci < 32; ci++) {
                            const float xv0 = xp[ci * 32768];
                            const float xv1 = xp[ci * 32768 + r1off];
                            const float* wc = wp + ci * 16;
#pragma unroll
                            for (int c = 0; c < 16; c++) {
                                acc0[c] += xv0 * wc[c];
                                acc1[c] += xv1 * wc[c];
                            }
                        }
                    }
                }
            }

            // mask out-of-range outputs (computed from clamped loads)
            if (!vlane) {
#pragma unroll
                for (int c = 0; c < 16; c++) { acc0[c] = 0.f; acc1[c] = 0.f; }
            } else if (!v1row) {
#pragma unroll
                for (int c = 0; c < 16; c++) acc1[c] = 0.f;
            }

            // BN stats + register-resident pool partials
#pragma unroll
            for (int c = 0; c < 16; c++) {
                ssum[c] += acc0[c] + acc1[c];
                ssq[c]  += acc0[c] * acc0[c] + acc1[c] * acc1[c];
            }
            if (poolok) {
#pragma unroll
                for (int c = 0; c < 16; c++) pacc[c] += acc0[c] + acc1[c];
            }
        }
    }

    // ---- exclusive pool write: combine lane pairs, STG raw sums ----
    {
        const int ph4 = half4 * 4 + ty;
        const int pw4 = ow2 >> 1;
        const size_t base =
            ((((size_t)n * 16) * 15 + a) * 15 + ph4) * 15 + pw4;
#pragma unroll
        for (int c = 0; c < 16; c++) {
            float p  = pacc[c];
            float p2 = __shfl_down_sync(0xffffffffu, p, 1);
            if (poolok && !(ow2 & 1))
                out[base + (size_t)c * 3375] = p + p2;
        }
    }

    // ---- stats reduce: warp shuffle -> smem -> 32 global atomics ----
#pragma unroll
    for (int c = 0; c < 16; c++) {
        float s = ssum[c], q = ssq[c];
#pragma unroll
        for (int o = 16; o >= 1; o >>= 1) {
            s += __shfl_xor_sync(0xffffffffu, s, o);
            q += __shfl_xor_sync(0xffffffffu, q, o);
        }
        if (tx == 0) {
            atomicAdd(&sred[c],      s);
            atomicAdd(&sred[16 + c], q);
        }
    }
    __syncthreads();
    if (tid < 16)      atomicAdd(&g_sum[tid],        sred[tid]);
    else if (tid < 32) atomicAdd(&g_sumsq[tid - 16], sred[tid]);
}

__global__ void stats_kernel(const float* __restrict__ gamma,
                             const float* __restrict__ beta) {
    int c = threadIdx.x;
    if (c >= 16) return;
    const float inv_cnt = 1.0f / 4000752.0f;   // 16 * 63^3
    float mean = g_sum[c] * inv_cnt;
    float var  = g_sumsq[c] * inv_cnt - mean * mean;
    float inv  = rsqrtf(var + 1e-5f);
    float sc   = gamma[c] * inv;
    g_scale[c] = sc;
    g_shift[c] = beta[c] - mean * sc;
}

// In-place: out currently holds raw 4x4x4 pool sums; apply mean + BN affine.
__global__ __launch_bounds__(256)
void affine_kernel(float* __restrict__ out) {
    int idx = blockIdx.x * 256 + threadIdx.x;
    if (idx >= 864000) return;
    int co = (idx / 3375) & 15;
    out[idx] = out[idx] * (1.0f / 64.0f) * g_scale[co] + g_shift[co];
}

extern "C" void kernel_launch(void* const* d_in, const int* in_sizes, int n_in,
                              void* d_out, int out_size) {
    const float* x     = (const float*)d_in[0];
    const float* w     = (const float*)d_in[1];
    const float* b     = (const float*)d_in[2];
    const float* gamma = (const float*)d_in[3];
    const float* beta  = (const float*)d_in[4];
    float* out = (float*)d_out;

    zero_stats_kernel<<<1, 32>>>();
    dim3 grid(4, 16, 16), blk(32, 4);
    conv_kernel<<<grid, blk>>>(x, w, b, out);
    stats_kernel<<<1, 16>>>(gamma, beta);
    affine_kernel<<<3375, 256>>>(out);
}

// round 4
// speedup vs baseline: 1.0119x; 1.0119x over previous
#include <cuda_runtime.h>

// ---------------------------------------------------------------------------
//   x:     (16, 32, 32, 32, 32) fp32
//   w:     (32, 16, 3, 3, 3)    fp32   (Cin, Cout, kd, kh, kw)
//   b, gamma, beta: (16,) fp32
//   ConvTranspose3d stride=2 pad=1 -> y (16,16,63,63,63)
//   BN over (N,D,H,W) per channel, AvgPool 4 (floor) -> (16,16,15,15,15)
//
// Parity decomposition (per axis): output o = 2*o2 + p.
//   p=0: 1 tap  (k=1, i=o2)        p=1: 2 taps (k=2,i=o2 ; k=0,i=o2+1)
// Pool: o/4 == a for od2 in {2a,2a+1}, both parities -> block owns pool
// slice a exclusively; pool sums live in registers, BN affine applied last.
// Inner loop uses packed fma.rn.f32x2 (2 MACs / fma-pipe issue slot).
// ---------------------------------------------------------------------------

typedef unsigned long long ull;

static __device__ float g_sum[16];
static __device__ float g_sumsq[16];
static __device__ float g_scale[16];
static __device__ float g_shift[16];

__device__ __forceinline__ ull pack2f(float a, float b) {
    ull r; asm("mov.b64 %0, {%1, %2};" : "=l"(r) : "f"(a), "f"(b)); return r;
}
__device__ __forceinline__ void unpack2f(ull v, float& a, float& b) {
    asm("mov.b64 {%0, %1}, %2;" : "=f"(a), "=f"(b) : "l"(v));
}
__device__ __forceinline__ void ffma2(ull& d, ull a, ull b) {
    asm("fma.rn.f32x2 %0, %1, %2, %0;" : "+l"(d) : "l"(a), "l"(b));
}

__global__ void zero_stats_kernel() {
    int t = threadIdx.x;
    if (t < 16) { g_sum[t] = 0.f; g_sumsq[t] = 0.f; }
}

// Grid: x = half4 (4: oh2 octet), y = a (16: od2 pair / pool-d), z = n (16).
// Block (32, 4). Thread: lane = ow2, warp ty -> oh2 rows {base, base+1},
// 16 cout as 8 packed f32x2 accumulators per row, 8 classes x 2 od2.
__global__ __launch_bounds__(128, 2)
void conv_kernel(const float* __restrict__ x,
                 const float* __restrict__ w,
                 const float* __restrict__ bias,
                 float* __restrict__ out)
{
    const int half4 = blockIdx.x;
    const int a     = blockIdx.y;
    const int n     = blockIdx.z;
    const int tx = threadIdx.x, ty = threadIdx.y;
    const int tid = ty * 32 + tx;
    const int ow2 = tx;
    const int oh2b = half4 * 8 + 2 * ty;      // even, 0..30

    __shared__ __align__(16) float ws[8 * 512];
    __shared__ float sred[32];
    __shared__ float bsh[16];

    if (tid < 32) sred[tid] = 0.f;
    if (tid < 16) bsh[tid] = bias[tid];

    float ssum[16], ssq[16], pacc[16];
#pragma unroll
    for (int c = 0; c < 16; c++) { ssum[c] = 0.f; ssq[c] = 0.f; pacc[c] = 0.f; }

    const bool poolok = (a < 15) && (oh2b < 30) && (ow2 < 30);

    for (int cls = 0; cls < 8; cls++) {
        const int pd = (cls >> 2) & 1, ph = (cls >> 1) & 1, pw = cls & 1;
        const int ntd = 1 + pd, nth = 1 + ph, ntw = 1 + pw;
        const int ntap = ntd * nth * ntw;

        __syncthreads();
        for (int i = tid; i < ntap * 512; i += 128) {
            int t = i >> 9, e = i & 511;
            int tw = t % ntw, th = (t / ntw) % nth, td = t / (ntw * nth);
            int kd = pd ? 2 - 2 * td : 1;
            int kh = ph ? 2 - 2 * th : 1;
            int kw = pw ? 2 - 2 * tw : 1;
            int ci = e >> 4, co = e & 15;
            ws[i] = w[(ci * 16 + co) * 27 + kd * 9 + kh * 3 + kw];
        }
        __syncthreads();

        const bool vlane = (!pw) || (ow2 < 31);       // ow = 2*ow2+pw <= 62
        const bool v1row = (!ph) || (oh2b + 1 < 31);  // row-1 oh <= 62
        const int  owS   = vlane ? ow2 : 0;           // clamp loads in-bounds
        const int  r1off = v1row ? 32 : 0;

        for (int dd = 0; dd < 2; dd++) {
            const int od2 = 2 * a + dd;
            if (pd && od2 == 31) continue;            // od = 63 (uniform skip)

            ull a0p[8], a1p[8];
#pragma unroll
            for (int j = 0; j < 8; j++) {
                ull bb = pack2f(bsh[2 * j], bsh[2 * j + 1]);
                a0p[j] = bb; a1p[j] = bb;
            }

            for (int td = 0; td < ntd; td++) {
                const int id = od2 + (pd ? td : 0);
                for (int th = 0; th < nth; th++) {
                    const int ih0 = oh2b + (ph ? th : 0);
                    for (int tw = 0; tw < ntw; tw++) {
                        const int iw = owS + (pw ? tw : 0);
                        const int tap = (td * nth + th) * ntw + tw;
                        const float* wp = ws + tap * 512;
                        const float* xp = x + (size_t)n * 1048576
                                            + (size_t)id * 1024 + ih0 * 32 + iw;
#pragma unroll 4
                        for (int ci = 0; ci < 32; ci++) {
                            const float xv0 = xp[ci * 32768];
                            const float xv1 = xp[ci * 32768 + r1off];
                            const ull xx0 = pack2f(xv0, xv0);
                            const ull xx1 = pack2f(xv1, xv1);
                            const ulonglong2* wv =
                                (const ulonglong2*)(wp + ci * 16);
#pragma unroll
                            for (int q = 0; q < 4; q++) {
                                ulonglong2 wq = wv[q];
                                ffma2(a0p[2 * q],     xx0, wq.x);
                                ffma2(a0p[2 * q + 1], xx0, wq.y);
                                ffma2(a1p[2 * q],     xx1, wq.x);
                                ffma2(a1p[2 * q + 1], xx1, wq.y);
                            }
                        }
                    }
                }
            }

            // unpack to scalars, mask out-of-range outputs
            float acc0[16], acc1[16];
#pragma unroll
            for (int j = 0; j < 8; j++) {
                unpack2f(a0p[j], acc0[2 * j], acc0[2 * j + 1]);
                unpack2f(a1p[j], acc1[2 * j], acc1[2 * j + 1]);
            }
            if (!vlane) {
#pragma unroll
                for (int c = 0; c < 16; c++) { acc0[c] = 0.f; acc1[c] = 0.f; }
            } else if (!v1row) {
#pragma unroll
                for (int c = 0; c < 16; c++) acc1[c] = 0.f;
            }

            // BN stats + register-resident pool partials
#pragma unroll
            for (int c = 0; c < 16; c++) {
                ssum[c] += acc0[c] + acc1[c];
                ssq[c]  += acc0[c] * acc0[c] + acc1[c] * acc1[c];
            }
            if (poolok) {
#pragma unroll
                for (int c = 0; c < 16; c++) pacc[c] += acc0[c] + acc1[c];
            }
        }
    }

    // ---- exclusive pool write: combine lane pairs, STG raw sums ----
    {
        const int ph4 = half4 * 4 + ty;
        const int pw4 = ow2 >> 1;
        const size_t base =
            ((((size_t)n * 16) * 15 + a) * 15 + ph4) * 15 + pw4;
#pragma unroll
        for (int c = 0; c < 16; c++) {
            float p  = pacc[c];
            float p2 = __shfl_down_sync(0xffffffffu, p, 1);
            if (poolok && !(ow2 & 1))
                out[base + (size_t)c * 3375] = p + p2;
        }
    }

    // ---- stats reduce: warp shuffle -> smem -> 32 global atomics ----
#pragma unroll
    for (int c = 0; c < 16; c++) {
        float s = ssum[c], q = ssq[c];
#pragma unroll
        for (int o = 16; o >= 1; o >>= 1) {
            s += __shfl_xor_sync(0xffffffffu, s, o);
            q += __shfl_xor_sync(0xffffffffu, q, o);
        }
        if (tx == 0) {
            atomicAdd(&sred[c],      s);
            atomicAdd(&sred[16 + c], q);
        }
    }
    __syncthreads();
    if (tid < 16)      atomicAdd(&g_sum[tid],        sred[tid]);
    else if (tid < 32) atomicAdd(&g_sumsq[tid - 16], sred[tid]);
}

__global__ void stats_kernel(const float* __restrict__ gamma,
                             const float* __restrict__ beta) {
    int c = threadIdx.x;
    if (c >= 16) return;
    const float inv_cnt = 1.0f / 4000752.0f;   // 16 * 63^3
    float mean = g_sum[c] * inv_cnt;
    float var  = g_sumsq[c] * inv_cnt - mean * mean;
    float inv  = rsqrtf(var + 1e-5f);
    float sc   = gamma[c] * inv;
    g_scale[c] = sc;
    g_shift[c] = beta[c] - mean * sc;
}

// In-place: out currently holds raw 4x4x4 pool sums; apply mean + BN affine.
__global__ __launch_bounds__(256)
void affine_kernel(float* __restrict__ out) {
    int idx = blockIdx.x * 256 + threadIdx.x;
    if (idx >= 864000) return;
    int co = (idx / 3375) & 15;
    out[idx] = out[idx] * (1.0f / 64.0f) * g_scale[co] + g_shift[co];
}

extern "C" void kernel_launch(void* const* d_in, const int* in_sizes, int n_in,
                              void* d_out, int out_size) {
    const float* x     = (const float*)d_in[0];
    const float* w     = (const float*)d_in[1];
    const float* b     = (const float*)d_in[2];
    const float* gamma = (const float*)d_in[3];
    const float* beta  = (const float*)d_in[4];
    float* out = (float*)d_out;

    zero_stats_kernel<<<1, 32>>>();
    dim3 grid(4, 16, 16), blk(32, 4);
    conv_kernel<<<grid, blk>>>(x, w, b, out);
    stats_kernel<<<1, 16>>>(gamma, beta);
    affine_kernel<<<3375, 256>>>(out);
}

// round 5
// speedup vs baseline: 1.6447x; 1.6254x over previous
#include <cuda_runtime.h>

// ---------------------------------------------------------------------------
//   x: (16,32,32,32,32) f32   w: (32,16,3,3,3)   b,gamma,beta: (16,)
//   ConvTranspose3d s=2 p=1 -> (16,16,63,63,63); BN; AvgPool4 -> (16,16,15,15,15)
//
// Parity classes (pd,ph,pw): o = 2*o2+p; p=0 -> tap k=1@i=o2; p=1 -> taps
// k=2@i=o2, k=0@i=o2+1. Pool cell o/4 = o2>>1 for both parities -> block
// owning od2 {2a,2a+1} x all classes owns pool slice a exclusively.
// For interior (poolok) threads the BN partial ssum IS the pool sum.
// Inner loops: packed fma.rn.f32x2; x neighborhood cached in registers per
// ci, w-neighbor taps obtained by lane shuffle (lane = ow2).
// ---------------------------------------------------------------------------

typedef unsigned long long ull;

static __device__ float g_sum[16];
static __device__ float g_sumsq[16];
static __device__ float g_scale[16];
static __device__ float g_shift[16];

__device__ __forceinline__ ull pack2f(float a, float b) {
    ull r; asm("mov.b64 %0, {%1, %2};" : "=l"(r) : "f"(a), "f"(b)); return r;
}
__device__ __forceinline__ void unpack2f(ull v, float& a, float& b) {
    asm("mov.b64 {%0, %1}, %2;" : "=f"(a), "=f"(b) : "l"(v));
}
__device__ __forceinline__ void ffma2(ull& d, ull a, ull b) {
    asm("fma.rn.f32x2 %0, %1, %2, %0;" : "+l"(d) : "l"(a), "l"(b));
}
__device__ __forceinline__ ull add2(ull a, ull b) {
    ull r; asm("add.rn.f32x2 %0, %1, %2;" : "=l"(r) : "l"(a), "l"(b)); return r;
}

__global__ void zero_stats_kernel() {
    int t = threadIdx.x;
    if (t < 16) { g_sum[t] = 0.f; g_sumsq[t] = 0.f; }
}

// One parity class, fully specialized. xq0 = x + n*1M + oh2b*32 + ow2.
template <int PD, int PH, int PW>
__device__ __forceinline__ void do_class(
    const float* __restrict__ xq0, const float* __restrict__ ws,
    const ull* __restrict__ bpak, int a, int hof2,
    bool vlane, bool v1row, ull* __restrict__ ssum, ull* __restrict__ ssq)
{
    const int NTD = 1 + PD, NTH = 1 + PH, NTW = 1 + PW;
    constexpr int UNR = (PD && PH) ? 2 : 4;

#pragma unroll 1
    for (int dd = 0; dd < 2; dd++) {
        const int od2 = 2 * a + dd;
        if (PD && od2 == 31) continue;          // od=63 invalid (uniform)
        const float* xq = xq0 + od2 * 1024;

        ull a0[8], a1[8];
#pragma unroll
        for (int j = 0; j < 8; j++) { a0[j] = bpak[j]; a1[j] = bpak[j]; }

#pragma unroll 1
        for (int ci0 = 0; ci0 < 32; ci0 += UNR) {
#pragma unroll
            for (int u = 0; u < UNR; u++) {
                const float* xp = xq + (ci0 + u) * 32768;
                // unique x neighborhood: [depth 0..NTD-1][row 0..NTH]
                float xr[2][3];
                xr[0][0] = xp[0];
                xr[0][1] = xp[32];
                if (PH) xr[0][2] = xp[hof2];
                if (PD) {
                    xr[1][0] = xp[1024];
                    xr[1][1] = xp[1056];
                    if (PH) xr[1][2] = xp[1024 + hof2];
                }
                ull xd[2][3], xs[2][3];
#pragma unroll
                for (int d = 0; d < NTD; d++)
#pragma unroll
                    for (int r = 0; r <= NTH; r++) {
                        xd[d][r] = pack2f(xr[d][r], xr[d][r]);
                        if (PW) {
                            float t = __shfl_down_sync(0xffffffffu, xr[d][r], 1);
                            xs[d][r] = pack2f(t, t);
                        }
                    }
#pragma unroll
                for (int td = 0; td < NTD; td++)
#pragma unroll
                    for (int th = 0; th < NTH; th++)
#pragma unroll
                        for (int tw = 0; tw < NTW; tw++) {
                            const int tap = (td * NTH + th) * NTW + tw;
                            const ulonglong2* wv = (const ulonglong2*)
                                (ws + tap * 512 + (ci0 + u) * 16);
                            const ull x0 = (PW && tw) ? xs[td][th]     : xd[td][th];
                            const ull x1 = (PW && tw) ? xs[td][th + 1] : xd[td][th + 1];
#pragma unroll
                            for (int q = 0; q < 4; q++) {
                                ulonglong2 wq = wv[q];
                                ffma2(a0[2 * q],     x0, wq.x);
                                ffma2(a0[2 * q + 1], x0, wq.y);
                                ffma2(a1[2 * q],     x1, wq.x);
                                ffma2(a1[2 * q + 1], x1, wq.y);
                            }
                        }
            }
        }

        // mask invalid outputs, then packed stats accumulate
        if (PW && !vlane) {
#pragma unroll
            for (int j = 0; j < 8; j++) { a0[j] = 0ull; a1[j] = 0ull; }
        } else if (PH && !v1row) {
#pragma unroll
            for (int j = 0; j < 8; j++) a1[j] = 0ull;
        }
#pragma unroll
        for (int j = 0; j < 8; j++) {
            ssum[j] = add2(ssum[j], add2(a0[j], a1[j]));
            ffma2(ssq[j], a0[j], a0[j]);
            ffma2(ssq[j], a1[j], a1[j]);
        }
    }
}

// Grid: x = half4 (4), y = a (16), z = n (16). Block (32,4).
// lane = ow2; warp ty -> output rows {oh2b, oh2b+1}; 16 cout packed.
__global__ __launch_bounds__(128, 4)
void conv_kernel(const float* __restrict__ x,
                 const float* __restrict__ w,
                 const float* __restrict__ bias,
                 float* __restrict__ out)
{
    const int half4 = blockIdx.x;
    const int a     = blockIdx.y;
    const int n     = blockIdx.z;
    const int tx = threadIdx.x, ty = threadIdx.y;
    const int tid = ty * 32 + tx;
    const int ow2 = tx;
    const int oh2b = half4 * 8 + 2 * ty;      // even, 0..30

    __shared__ __align__(16) float ws[8 * 512];
    __shared__ float sred[32];
    __shared__ float bsh[16];

    if (tid < 32) sred[tid] = 0.f;
    if (tid < 16) bsh[tid] = bias[tid];

    ull ssum[8], ssq[8];
#pragma unroll
    for (int j = 0; j < 8; j++) { ssum[j] = 0ull; ssq[j] = 0ull; }

    const int hof2 = (oh2b == 30) ? 32 : 64;  // clamped row oh2b+2 offset
    const float* xq0 = x + (size_t)n * 1048576 + oh2b * 32 + ow2;
    const bool poolok = (a < 15) && (oh2b < 30) && (ow2 < 30);

    for (int cls = 0; cls < 8; cls++) {
        const int pd = (cls >> 2) & 1, ph = (cls >> 1) & 1, pw = cls & 1;
        const int ntd = 1 + pd, nth = 1 + ph, ntw = 1 + pw;
        const int ntap = ntd * nth * ntw;

        __syncthreads();
        for (int i = tid; i < ntap * 512; i += 128) {
            int t = i >> 9, e = i & 511;
            int tw = t % ntw, th = (t / ntw) % nth, td = t / (ntw * nth);
            int kd = pd ? 2 - 2 * td : 1;
            int kh = ph ? 2 - 2 * th : 1;
            int kw = pw ? 2 - 2 * tw : 1;
            int ci = e >> 4, co = e & 15;
            ws[i] = w[(ci * 16 + co) * 27 + kd * 9 + kh * 3 + kw];
        }
        __syncthreads();

        ull bpak[8];
#pragma unroll
        for (int j = 0; j < 8; j++) bpak[j] = pack2f(bsh[2 * j], bsh[2 * j + 1]);

        const bool vlane = (!pw) || (ow2 < 31);
        const bool v1row = (!ph) || (oh2b < 30);

        switch (cls) {
            case 0: do_class<0,0,0>(xq0, ws, bpak, a, hof2, vlane, v1row, ssum, ssq); break;
            case 1: do_class<0,0,1>(xq0, ws, bpak, a, hof2, vlane, v1row, ssum, ssq); break;
            case 2: do_class<0,1,0>(xq0, ws, bpak, a, hof2, vlane, v1row, ssum, ssq); break;
            case 3: do_class<0,1,1>(xq0, ws, bpak, a, hof2, vlane, v1row, ssum, ssq); break;
            case 4: do_class<1,0,0>(xq0, ws, bpak, a, hof2, vlane, v1row, ssum, ssq); break;
            case 5: do_class<1,0,1>(xq0, ws, bpak, a, hof2, vlane, v1row, ssum, ssq); break;
            case 6: do_class<1,1,0>(xq0, ws, bpak, a, hof2, vlane, v1row, ssum, ssq); break;
            case 7: do_class<1,1,1>(xq0, ws, bpak, a, hof2, vlane, v1row, ssum, ssq); break;
        }
    }

    // ---- pool write straight from ssum (== pool sum for poolok threads) ----
    {
        const int ph4 = half4 * 4 + ty;
        const int pw4 = ow2 >> 1;
        const size_t base =
            ((((size_t)n * 16) * 15 + a) * 15 + ph4) * 15 + pw4;
#pragma unroll
        for (int j = 0; j < 8; j++) {
            float sl, sh;
            unpack2f(ssum[j], sl, sh);
            float sl2 = __shfl_down_sync(0xffffffffu, sl, 1);
            float sh2 = __shfl_down_sync(0xffffffffu, sh, 1);
            if (poolok && !(ow2 & 1)) {
                out[base + (size_t)(2 * j)     * 3375] = sl + sl2;
                out[base + (size_t)(2 * j + 1) * 3375] = sh + sh2;
            }
        }
    }

    // ---- stats reduce: warp shuffle -> smem -> 32 global atomics ----
#pragma unroll
    for (int j = 0; j < 8; j++) {
        float sl, sh, ql, qh;
        unpack2f(ssum[j], sl, sh);
        unpack2f(ssq[j],  ql, qh);
#pragma unroll
        for (int o = 16; o >= 1; o >>= 1) {
            sl += __shfl_xor_sync(0xffffffffu, sl, o);
            sh += __shfl_xor_sync(0xffffffffu, sh, o);
            ql += __shfl_xor_sync(0xffffffffu, ql, o);
            qh += __shfl_xor_sync(0xffffffffu, qh, o);
        }
        if (tx == 0) {
            atomicAdd(&sred[2 * j],          sl);
            atomicAdd(&sred[2 * j + 1],      sh);
            atomicAdd(&sred[16 + 2 * j],     ql);
            atomicAdd(&sred[16 + 2 * j + 1], qh);
        }
    }
    __syncthreads();
    if (tid < 16)      atomicAdd(&g_sum[tid],        sred[tid]);
    else if (tid < 32) atomicAdd(&g_sumsq[tid - 16], sred[tid]);
}

__global__ void stats_kernel(const float* __restrict__ gamma,
                             const float* __restrict__ beta) {
    int c = threadIdx.x;
    if (c >= 16) return;
    const float inv_cnt = 1.0f / 4000752.0f;   // 16 * 63^3
    float mean = g_sum[c] * inv_cnt;
    float var  = g_sumsq[c] * inv_cnt - mean * mean;
    float inv  = rsqrtf(var + 1e-5f);
    float sc   = gamma[c] * inv;
    g_scale[c] = sc;
    g_shift[c] = beta[c] - mean * sc;
}

__global__ __launch_bounds__(256)
void affine_kernel(float* __restrict__ out) {
    int idx = blockIdx.x * 256 + threadIdx.x;
    if (idx >= 864000) return;
    int co = (idx / 3375) & 15;
    out[idx] = out[idx] * (1.0f / 64.0f) * g_scale[co] + g_shift[co];
}

extern "C" void kernel_launch(void* const* d_in, const int* in_sizes, int n_in,
                              void* d_out, int out_size) {
    const float* x     = (const float*)d_in[0];
    const float* w     = (const float*)d_in[1];
    const float* b     = (const float*)d_in[2];
    const float* gamma = (const float*)d_in[3];
    const float* beta  = (const float*)d_in[4];
    float* out = (float*)d_out;

    zero_stats_kernel<<<1, 32>>>();
    dim3 grid(4, 16, 16), blk(32, 4);
    conv_kernel<<<grid, blk>>>(x, w, b, out);
    stats_kernel<<<1, 16>>>(gamma, beta);
    affine_kernel<<<3375, 256>>>(out);
}